// round 15
// baseline (speedup 1.0000x reference)
#include <cuda_runtime.h>
#include <math.h>

// Problem constants (from reference)
#define NPROJS 128
#define L_DIM  1024
#define S_DIM  256
#define SPACING 4.7952f
#define MU0     0.013f

#define NBLOCKS 128            // one wave; measured-optimal grid shape
#define ROWS_PER_BLOCK 8       // one warp per row, 256 threads/block

// Packed accumulator: bits [0:56) fixed-point sum (scale 2^40),
//                     bits [56:64) arrival count.
__device__ unsigned long long g_acc = 0ULL;

#define FIX_SCALE   1099511627776.0f      /* 2^40 */
#define FIX_INV     (1.0 / 1099511627776.0)
#define COUNT_ONE   (1ULL << 56)
#define SUM_MASK    ((1ULL << 56) - 1ULL)

// 32-byte (8-float) vector view: eligible for LDG.E.256 on sm_100+.
union V8 { ulonglong4 u; float f[8]; };

__global__ void __launch_bounds__(256) edcc_fused_kernel(
    const float* __restrict__ projs, float sigma, float* __restrict__ out)
{
    const int lane = threadIdx.x & 31;
    const int warp = threadIdx.x >> 5;      // 0..7 -> row within block
    const int l = blockIdx.x * ROWS_PER_BLOCK + warp;

    // Two used projection slices (i=127, j=29); one warp handles row l.
    // Lane t owns elements [8t, 8t+8) of the 256-element row: one 32B load
    // per slice per thread (2 LDGs instead of 4).
    const ulonglong4* __restrict__ pi = (const ulonglong4*)(projs
        + (size_t)127 * L_DIM * S_DIM + (size_t)l * S_DIM);
    const ulonglong4* __restrict__ pj = (const ulonglong4*)(projs
        + (size_t)29  * L_DIM * S_DIM + (size_t)l * S_DIM);

    // Front-batch both independent 32B loads
    V8 a, b;
    a.u = pi[lane];
    b.u = pj[lane];

    // Weight: w(e) = exp(sigma * s(e) * SPACING), s(e) = s_start + e*SPACING
    // (MUFU work overlaps the in-flight loads)
    const float s_start = (-(float)S_DIM * SPACING + SPACING) * 0.5f;
    const float c1 = sigma * SPACING;
    const float base = c1 * s_start;
    const float step = c1 * SPACING;
    const int e0 = lane * 8;

    float vi = 0.0f, vj = 0.0f;
    #pragma unroll
    for (int k = 0; k < 8; k++) {
        const float w = __expf(base + (float)(e0 + k) * step);
        vi += a.f[k] * w;
        vj += b.f[k] * w;
    }

    // Warp reduction -> P_i, P_j for this row
    #pragma unroll
    for (int off = 16; off > 0; off >>= 1) {
        vi += __shfl_down_sync(0xFFFFFFFFu, vi, off);
        vj += __shfl_down_sync(0xFFFFFFFFu, vj, off);
    }

    __shared__ float sh_terms[ROWS_PER_BLOCK];
    if (lane == 0) {
        const float den = vi + vj;
        sh_terms[warp] = (den != 0.0f)
                       ? (2.0f / (float)NPROJS) * fabsf(vi - vj) / den
                       : 0.0f;
    }
    __syncthreads();

    if (threadIdx.x == 0) {
        float bsum = 0.0f;
        #pragma unroll
        for (int k = 0; k < ROWS_PER_BLOCK; k++) bsum += sh_terms[k];

        // Fixed-point contribution + arrival count in ONE atomic.
        // Integer adds commute -> result is bitwise deterministic.
        const unsigned long long contrib =
            (unsigned long long)(bsum * FIX_SCALE) | COUNT_ONE;
        const unsigned long long old = atomicAdd(&g_acc, contrib);

        if ((old >> 56) == (unsigned long long)(NBLOCKS - 1)) {
            const unsigned long long total = (old + contrib) & SUM_MASK;
            out[0] = (float)((double)total * FIX_INV);  // mean over B=1
            g_acc = 0ULL;   // re-arm for next graph replay
        }
    }
}

extern "C" void kernel_launch(void* const* d_in, const int* in_sizes, int n_in,
                              void* d_out, int out_size)
{
    const float* projs = (const float*)d_in[0];
    float* out = (float*)d_out;

    // sigma = MU0 * tan((theta[127] - theta[29]) / 2), theta_k = 2*pi*k/128
    const double two_pi = 6.283185307179586;
    const double th_i = two_pi * 127.0 / 128.0;
    const double th_j = two_pi * 29.0 / 128.0;
    const float sigma = (float)((double)MU0 * tan((th_i - th_j) * 0.5));

    edcc_fused_kernel<<<NBLOCKS, 256>>>(projs, sigma, out);
}

// round 16
// speedup vs baseline: 1.0047x; 1.0047x over previous
#include <cuda_runtime.h>
#include <math.h>

// Problem constants (from reference)
#define NPROJS 128
#define L_DIM  1024
#define S_DIM  256
#define SPACING 4.7952f
#define MU0     0.013f

#define NBLOCKS 128            // one wave; measured-optimal grid shape
#define ROWS_PER_BLOCK 8       // one warp per row, 256 threads/block

// Packed accumulator: bits [0:56) fixed-point sum (scale 2^40),
//                     bits [56:64) arrival count. Zero at load; last
// arrival resets it for the next graph replay.
__device__ unsigned long long g_acc = 0ULL;

#define FIX_SCALE   1099511627776.0f      /* 2^40 */
#define FIX_INV     (1.0 / 1099511627776.0)
#define COUNT_ONE   (1ULL << 56)
#define SUM_MASK    ((1ULL << 56) - 1ULL)

__global__ void __launch_bounds__(256) edcc_fused_kernel(
    const float* __restrict__ projs, float sigma, float* __restrict__ out)
{
    const int lane = threadIdx.x & 31;
    const int warp = threadIdx.x >> 5;      // 0..7 -> row within block
    const int l = blockIdx.x * ROWS_PER_BLOCK + warp;

    // Two used projection slices (i=127, j=29); one warp handles row l.
    const float4* __restrict__ pi = (const float4*)(projs
        + (size_t)127 * L_DIM * S_DIM + (size_t)l * S_DIM);
    const float4* __restrict__ pj = (const float4*)(projs
        + (size_t)29  * L_DIM * S_DIM + (size_t)l * S_DIM);

    // Front-batch all 4 independent 16B loads (max MLP before any use)
    const float4 a0 = pi[lane];
    const float4 a1 = pi[lane + 32];
    const float4 b0 = pj[lane];
    const float4 b1 = pj[lane + 32];

    // Weight: w(e) = exp(sigma * s(e) * SPACING), s(e) = s_start + e*SPACING
    // (MUFU work overlaps the in-flight loads)
    const float s_start = (-(float)S_DIM * SPACING + SPACING) * 0.5f;
    const float c1 = sigma * SPACING;
    const float base = c1 * s_start;
    const float step = c1 * SPACING;

    float vi, vj;
    {
        const int e0 = lane * 4;
        const float w0 = __expf(base + (float)(e0 + 0) * step);
        const float w1 = __expf(base + (float)(e0 + 1) * step);
        const float w2 = __expf(base + (float)(e0 + 2) * step);
        const float w3 = __expf(base + (float)(e0 + 3) * step);
        const int e1 = (lane + 32) * 4;
        const float u0 = __expf(base + (float)(e1 + 0) * step);
        const float u1 = __expf(base + (float)(e1 + 1) * step);
        const float u2 = __expf(base + (float)(e1 + 2) * step);
        const float u3 = __expf(base + (float)(e1 + 3) * step);

        vi = a0.x * w0 + a0.y * w1 + a0.z * w2 + a0.w * w3
           + a1.x * u0 + a1.y * u1 + a1.z * u2 + a1.w * u3;
        vj = b0.x * w0 + b0.y * w1 + b0.z * w2 + b0.w * w3
           + b1.x * u0 + b1.y * u1 + b1.z * u2 + b1.w * u3;
    }

    // Warp reduction -> P_i, P_j for this row
    #pragma unroll
    for (int off = 16; off > 0; off >>= 1) {
        vi += __shfl_down_sync(0xFFFFFFFFu, vi, off);
        vj += __shfl_down_sync(0xFFFFFFFFu, vj, off);
    }

    __shared__ float sh_terms[ROWS_PER_BLOCK];
    if (lane == 0) {
        const float den = vi + vj;
        sh_terms[warp] = (den != 0.0f)
                       ? (2.0f / (float)NPROJS) * fabsf(vi - vj) / den
                       : 0.0f;
    }
    __syncthreads();

    if (threadIdx.x == 0) {
        float bsum = 0.0f;
        #pragma unroll
        for (int k = 0; k < ROWS_PER_BLOCK; k++) bsum += sh_terms[k];

        // Fixed-point contribution + arrival count in ONE atomic.
        // Integer adds commute -> result is bitwise deterministic.
        const unsigned long long contrib =
            (unsigned long long)(bsum * FIX_SCALE) | COUNT_ONE;
        const unsigned long long old = atomicAdd(&g_acc, contrib);

        if ((old >> 56) == (unsigned long long)(NBLOCKS - 1)) {
            const unsigned long long total = (old + contrib) & SUM_MASK;
            out[0] = (float)((double)total * FIX_INV);  // mean over B=1 -> identity
            g_acc = 0ULL;   // re-arm for next graph replay (same-thread ordering)
        }
    }
}

extern "C" void kernel_launch(void* const* d_in, const int* in_sizes, int n_in,
                              void* d_out, int out_size)
{
    const float* projs = (const float*)d_in[0];
    float* out = (float*)d_out;

    // sigma = MU0 * tan((theta[127] - theta[29]) / 2), theta_k = 2*pi*k/128
    const double two_pi = 6.283185307179586;
    const double th_i = two_pi * 127.0 / 128.0;
    const double th_j = two_pi * 29.0 / 128.0;
    const float sigma = (float)((double)MU0 * tan((th_i - th_j) * 0.5));

    edcc_fused_kernel<<<NBLOCKS, 256>>>(projs, sigma, out);
}

// round 17
// speedup vs baseline: 1.0385x; 1.0337x over previous
#include <cuda_runtime.h>
#include <math.h>

// Problem constants (from reference)
#define NPROJS 128
#define L_DIM  1024
#define S_DIM  256
#define SPACING 4.7952f
#define MU0     0.013f

#define NBLOCKS 128            // proven-optimal grid
#define NTHREADS 512           // 16 warps/SM: 2 half-row warps per row
#define ROWS_PER_BLOCK 8

// Packed accumulator: bits [0:56) fixed-point sum (scale 2^40),
//                     bits [56:64) arrival count (128).
__device__ unsigned long long g_acc = 0ULL;

#define FIX_SCALE   1099511627776.0f      /* 2^40 */
#define FIX_INV     (1.0 / 1099511627776.0)
#define COUNT_ONE   (1ULL << 56)
#define SUM_MASK    ((1ULL << 56) - 1ULL)

__global__ void __launch_bounds__(NTHREADS) edcc_fused_kernel(
    const float* __restrict__ projs, float sigma, float* __restrict__ out)
{
    const int lane = threadIdx.x & 31;
    const int warp = threadIdx.x >> 5;       // 0..15
    const int row  = warp >> 1;              // 0..7 row within block
    const int half = warp & 1;               // 0 = elements [0,128), 1 = [128,256)
    const int l = blockIdx.x * ROWS_PER_BLOCK + row;

    // Two used projection slices (i=127, j=29); this warp handles one
    // half-row: lane t owns float4 index (half*32 + t).
    const float4* __restrict__ pi = (const float4*)(projs
        + (size_t)127 * L_DIM * S_DIM + (size_t)l * S_DIM);
    const float4* __restrict__ pj = (const float4*)(projs
        + (size_t)29  * L_DIM * S_DIM + (size_t)l * S_DIM);
    const int f = half * 32 + lane;

    // ONE LDG.128 per slice per thread; 4x the warps issuing in parallel.
    const float4 a = pi[f];
    const float4 b = pj[f];

    // Weight: w(e) = exp(sigma * s(e) * SPACING), s(e) = s_start + e*SPACING
    // (MUFU work overlaps the in-flight loads)
    const float s_start = (-(float)S_DIM * SPACING + SPACING) * 0.5f;
    const float c1 = sigma * SPACING;
    const float base = c1 * s_start;
    const float step = c1 * SPACING;

    const int e = f * 4;
    const float w0 = __expf(base + (float)(e + 0) * step);
    const float w1 = __expf(base + (float)(e + 1) * step);
    const float w2 = __expf(base + (float)(e + 2) * step);
    const float w3 = __expf(base + (float)(e + 3) * step);

    float vi = a.x * w0 + a.y * w1 + a.z * w2 + a.w * w3;
    float vj = b.x * w0 + b.y * w1 + b.z * w2 + b.w * w3;

    // Warp reduction -> half-row partial sums
    #pragma unroll
    for (int off = 16; off > 0; off >>= 1) {
        vi += __shfl_down_sync(0xFFFFFFFFu, vi, off);
        vj += __shfl_down_sync(0xFFFFFFFFu, vj, off);
    }

    __shared__ float2 sh_part[16];           // per-warp (vi, vj) partials
    if (lane == 0) sh_part[warp] = make_float2(vi, vj);
    __syncthreads();

    // Warp 0: lanes 0..7 each combine one row's two halves (low + high,
    // preserving the original left-to-right FP32 sum order), compute the
    // term, 3-shuffle sum, then ONE packed deterministic atomic.
    if (warp == 0) {
        float term = 0.0f;
        if (lane < ROWS_PER_BLOCK) {
            const float2 lo = sh_part[lane * 2];
            const float2 hi = sh_part[lane * 2 + 1];
            const float Pi = lo.x + hi.x;
            const float Pj = lo.y + hi.y;
            const float den = Pi + Pj;
            term = (den != 0.0f)
                 ? (2.0f / (float)NPROJS) * fabsf(Pi - Pj) / den
                 : 0.0f;
        }
        term += __shfl_down_sync(0xFFFFFFFFu, term, 4);
        term += __shfl_down_sync(0xFFFFFFFFu, term, 2);
        term += __shfl_down_sync(0xFFFFFFFFu, term, 1);

        if (lane == 0) {
            // Integer adds commute -> bitwise deterministic across replays.
            const unsigned long long contrib =
                (unsigned long long)(term * FIX_SCALE) | COUNT_ONE;
            const unsigned long long old = atomicAdd(&g_acc, contrib);

            if ((old >> 56) == (unsigned long long)(NBLOCKS - 1)) {
                const unsigned long long total = (old + contrib) & SUM_MASK;
                out[0] = (float)((double)total * FIX_INV);  // mean over B=1
                g_acc = 0ULL;   // re-arm for next graph replay
            }
        }
    }
}

extern "C" void kernel_launch(void* const* d_in, const int* in_sizes, int n_in,
                              void* d_out, int out_size)
{
    const float* projs = (const float*)d_in[0];
    float* out = (float*)d_out;

    // sigma = MU0 * tan((theta[127] - theta[29]) / 2), theta_k = 2*pi*k/128
    const double two_pi = 6.283185307179586;
    const double th_i = two_pi * 127.0 / 128.0;
    const double th_j = two_pi * 29.0 / 128.0;
    const float sigma = (float)((double)MU0 * tan((th_i - th_j) * 0.5));

    edcc_fused_kernel<<<NBLOCKS, NTHREADS>>>(projs, sigma, out);
}